// round 10
// baseline (speedup 1.0000x reference)
#include <cuda_runtime.h>
#include <cstdint>

#define NMAT    128
#define N       256
#define THREADS 1024

// smem (bytes): W4 131072 | part 16384 | c2 512 | cvec 1024
#define SMEM_BYTES (131072 + 16384 + 512 + 1024)

__device__ __forceinline__ uint32_t hfma2(uint32_t a, uint32_t b, uint32_t c) {
    uint32_t d; asm("fma.rn.f16x2 %0,%1,%2,%3;" : "=r"(d) : "r"(a), "r"(b), "r"(c)); return d;
}
__device__ __forceinline__ uint32_t hmul2(uint32_t a, uint32_t b) {
    uint32_t d; asm("mul.rn.f16x2 %0,%1,%2;" : "=r"(d) : "r"(a), "r"(b)); return d;
}
__device__ __forceinline__ uint32_t hadd2(uint32_t a, uint32_t b) {
    uint32_t d; asm("add.rn.f16x2 %0,%1,%2;" : "=r"(d) : "r"(a), "r"(b)); return d;
}
__device__ __forceinline__ uint32_t pk(float lo, float hi) {
    uint32_t d; asm("cvt.rn.f16x2.f32 %0, %1, %2;" : "=r"(d) : "f"(hi), "f"(lo)); return d;
}
__device__ __forceinline__ void h2f2(uint32_t w, float& lo, float& hi) {
    asm("{\n\t.reg .f16 l, h;\n\tmov.b32 {l, h}, %2;\n\tcvt.f32.f16 %0, l;\n\tcvt.f32.f16 %1, h;\n\t}"
        : "=f"(lo), "=f"(hi) : "r"(w));
}
__device__ __forceinline__ float frcp(float x) {
    float r; asm("rcp.approx.f32 %0, %1;" : "=f"(r) : "f"(x)); return r;
}
__device__ __forceinline__ void stcs4(float4* p, float4 v) {
    asm volatile("st.global.cs.v4.f32 [%0], {%1,%2,%3,%4};"
                 :: "l"(p), "f"(v.x), "f"(v.y), "f"(v.z), "f"(v.w) : "memory");
}

__global__ void __launch_bounds__(THREADS, 1)
sinkhorn_kernel(const float* __restrict__ x, float* __restrict__ y)
{
    extern __shared__ uint32_t smem_raw[];
    uint4*    W4   = (uint4*)smem_raw;                  // [256][32] chunks, XOR-swizzled
    uint4*    part = (uint4*)(smem_raw + 32768);        // [32][32] partial tile (reused)
    uint32_t* c2   = smem_raw + 36864;                  // [128] f16x2 (1/S1 pairs)
    float*    cvec = (float*)(smem_raw + 36992);        // [256] f32 (1/S2)

    const int tid = threadIdx.x;
    const int w   = tid >> 5;       // warp 0..31
    const int l   = tid & 31;       // lane
    const int g   = l >> 3;         // 8-lane group 0..3
    const int sub = l & 7;          // lane-in-group

    const float* __restrict__ X = x + (size_t)blockIdx.x * (N * N);
    float*       __restrict__ Y = y + (size_t)blockIdx.x * (N * N);

    // ==== Load fp32 -> fp16x2 smem (XOR swizzle) + fused iter-1 Phase A partials ====
    {
        const float4* __restrict__ Xv = (const float4*)X;
        float s0=0.f,s1=0.f,s2=0.f,s3=0.f,s4=0.f,s5=0.f,s6=0.f,s7=0.f;
        #pragma unroll 4
        for (int k = 0; k < 8; ++k) {
            const int row = w + (k << 5);
            const int lin = (row << 5) | l;
            float4 a = Xv[2 * lin];
            float4 b = Xv[2 * lin + 1];
            uint4 wv;
            wv.x = pk(a.x, a.y); wv.y = pk(a.z, a.w);
            wv.z = pk(b.x, b.y); wv.w = pk(b.z, b.w);
            W4[(row << 5) | (l ^ w)] = wv;
            s0 += a.x; s1 += a.y; s2 += a.z; s3 += a.w;
            s4 += b.x; s5 += b.y; s6 += b.z; s7 += b.w;
        }
        uint4 pv;
        pv.x = pk(s0, s1); pv.y = pk(s2, s3);
        pv.z = pk(s4, s5); pv.w = pk(s6, s7);
        part[(w << 5) | (l ^ w)] = pv;       // logical part[rg=w][chunk=l]
    }
    __syncthreads();

    // ==== A1 reduce: warp w reduces chunk-column w -> c2 ====
    {
        uint4 pv = part[(l << 5) | (w ^ l)];  // logical part[rg=l][chunk=w]
        uint32_t a0 = pv.x, a1 = pv.y, a2 = pv.z, a3 = pv.w;
        #pragma unroll
        for (int o = 16; o; o >>= 1) {
            a0 = hadd2(a0, __shfl_xor_sync(0xffffffffu, a0, o));
            a1 = hadd2(a1, __shfl_xor_sync(0xffffffffu, a1, o));
            a2 = hadd2(a2, __shfl_xor_sync(0xffffffffu, a2, o));
            a3 = hadd2(a3, __shfl_xor_sync(0xffffffffu, a3, o));
        }
        if (l < 4) {
            uint32_t s = (l == 0) ? a0 : (l == 1) ? a1 : (l == 2) ? a2 : a3;
            float lo, hi; h2f2(s, lo, hi);
            c2[(w << 2) | l] = pk(frcp(lo), frcp(hi));
        }
    }
    __syncthreads();

    // ==== B1 (fp16 row sums with c1) FUSED with A2 partial accumulation ====
    {
        uint32_t acc[16];
        #pragma unroll
        for (int j = 0; j < 16; ++j) acc[j] = 0u;

        #pragma unroll
        for (int step = 0; step < 2; ++step) {
            const int i  = (w << 3) | (step << 2) | g;
            const int m  = i & 31;
            const int rb = i << 5;
            uint4 xq0, xq1, xq2, xq3;
            uint32_t p0, p1, p2, p3;
            {
                xq0 = W4[rb | ( sub        ^ m)];
                const uint4 cq = ((const uint4*)c2)[sub];
                p0 = hmul2(xq0.x, cq.x);
                p0 = hfma2(xq0.y, cq.y, p0); p0 = hfma2(xq0.z, cq.z, p0); p0 = hfma2(xq0.w, cq.w, p0);
            }
            {
                xq1 = W4[rb | ((sub +  8) ^ m)];
                const uint4 cq = ((const uint4*)c2)[sub + 8];
                p1 = hmul2(xq1.x, cq.x);
                p1 = hfma2(xq1.y, cq.y, p1); p1 = hfma2(xq1.z, cq.z, p1); p1 = hfma2(xq1.w, cq.w, p1);
            }
            {
                xq2 = W4[rb | ((sub + 16) ^ m)];
                const uint4 cq = ((const uint4*)c2)[sub + 16];
                p2 = hmul2(xq2.x, cq.x);
                p2 = hfma2(xq2.y, cq.y, p2); p2 = hfma2(xq2.z, cq.z, p2); p2 = hfma2(xq2.w, cq.w, p2);
            }
            {
                xq3 = W4[rb | ((sub + 24) ^ m)];
                const uint4 cq = ((const uint4*)c2)[sub + 24];
                p3 = hmul2(xq3.x, cq.x);
                p3 = hfma2(xq3.y, cq.y, p3); p3 = hfma2(xq3.z, cq.z, p3); p3 = hfma2(xq3.w, cq.w, p3);
            }
            uint32_t ps = hadd2(hadd2(p0, p1), hadd2(p2, p3));
            float lo, hi; h2f2(ps, lo, hi);
            float t = lo + hi;
            t += __shfl_xor_sync(0xffffffffu, t, 1);
            t += __shfl_xor_sync(0xffffffffu, t, 2);
            t += __shfl_xor_sync(0xffffffffu, t, 4);
            const float r = frcp(t);
            const uint32_t rp = pk(r, r);
            acc[0]  = hfma2(rp, xq0.x, acc[0]);  acc[1]  = hfma2(rp, xq0.y, acc[1]);
            acc[2]  = hfma2(rp, xq0.z, acc[2]);  acc[3]  = hfma2(rp, xq0.w, acc[3]);
            acc[4]  = hfma2(rp, xq1.x, acc[4]);  acc[5]  = hfma2(rp, xq1.y, acc[5]);
            acc[6]  = hfma2(rp, xq1.z, acc[6]);  acc[7]  = hfma2(rp, xq1.w, acc[7]);
            acc[8]  = hfma2(rp, xq2.x, acc[8]);  acc[9]  = hfma2(rp, xq2.y, acc[9]);
            acc[10] = hfma2(rp, xq2.z, acc[10]); acc[11] = hfma2(rp, xq2.w, acc[11]);
            acc[12] = hfma2(rp, xq3.x, acc[12]); acc[13] = hfma2(rp, xq3.y, acc[13]);
            acc[14] = hfma2(rp, xq3.z, acc[14]); acc[15] = hfma2(rp, xq3.w, acc[15]);
        }
        // reduce over the 4 lane-groups (same sub, g=0..3)
        #pragma unroll
        for (int j = 0; j < 16; ++j) {
            acc[j] = hadd2(acc[j], __shfl_xor_sync(0xffffffffu, acc[j], 8));
            acc[j] = hadd2(acc[j], __shfl_xor_sync(0xffffffffu, acc[j], 16));
        }
        if (l < 8) {          // lane sub==l holds warp partials for chunks {l, l+8, l+16, l+24}
            #pragma unroll
            for (int q = 0; q < 4; ++q) {
                const int c = l + (q << 3);
                uint4 v;
                v.x = acc[q * 4 + 0]; v.y = acc[q * 4 + 1];
                v.z = acc[q * 4 + 2]; v.w = acc[q * 4 + 3];
                part[(w << 5) | (c ^ w)] = v;    // logical part[v=w][chunk=c]
            }
        }
    }
    __syncthreads();

    // ==== A2 reduce (fp32 butterfly over 32 warp-partials) -> cvec ====
    {
        uint4 pv = part[(l << 5) | (w ^ l)];     // logical part[v=l][chunk=w]
        float s0,s1,s2,s3,s4,s5,s6,s7;
        h2f2(pv.x, s0, s1); h2f2(pv.y, s2, s3);
        h2f2(pv.z, s4, s5); h2f2(pv.w, s6, s7);
        #pragma unroll
        for (int o = 16; o; o >>= 1) {
            s0 += __shfl_xor_sync(0xffffffffu, s0, o);
            s1 += __shfl_xor_sync(0xffffffffu, s1, o);
            s2 += __shfl_xor_sync(0xffffffffu, s2, o);
            s3 += __shfl_xor_sync(0xffffffffu, s3, o);
            s4 += __shfl_xor_sync(0xffffffffu, s4, o);
            s5 += __shfl_xor_sync(0xffffffffu, s5, o);
            s6 += __shfl_xor_sync(0xffffffffu, s6, o);
            s7 += __shfl_xor_sync(0xffffffffu, s7, o);
        }
        if (l < 8) {
            float v = (l==0)?s0:(l==1)?s1:(l==2)?s2:(l==3)?s3:(l==4)?s4:(l==5)?s5:(l==6)?s6:s7;
            cvec[(w << 3) | l] = frcp(v);
        }
    }
    __syncthreads();

    // ==== B2 (fp32 row sums with c2) FUSED with output write ====
    {
        #pragma unroll
        for (int step = 0; step < 2; ++step) {
            const int i  = (w << 3) | (step << 2) | g;
            const int m  = i & 31;
            const int rb = i << 5;
            float ta = 0.f, tb = 0.f;
            #pragma unroll
            for (int q = 0; q < 4; ++q) {
                const int lc = sub + (q << 3);
                uint4 xv = W4[rb | (lc ^ m)];
                float4 ca = ((const float4*)cvec)[lc * 2];
                float4 cb = ((const float4*)cvec)[lc * 2 + 1];
                float f0,f1,f2,f3,f4,f5,f6,f7;
                h2f2(xv.x, f0, f1); h2f2(xv.y, f2, f3);
                h2f2(xv.z, f4, f5); h2f2(xv.w, f6, f7);
                ta = fmaf(f0, ca.x, ta); tb = fmaf(f1, ca.y, tb);
                ta = fmaf(f2, ca.z, ta); tb = fmaf(f3, ca.w, tb);
                ta = fmaf(f4, cb.x, ta); tb = fmaf(f5, cb.y, tb);
                ta = fmaf(f6, cb.z, ta); tb = fmaf(f7, cb.w, tb);
            }
            float t = ta + tb;
            t += __shfl_xor_sync(0xffffffffu, t, 1);
            t += __shfl_xor_sync(0xffffffffu, t, 2);
            t += __shfl_xor_sync(0xffffffffu, t, 4);
            const float r = frcp(t);

            #pragma unroll
            for (int q = 0; q < 4; ++q) {
                const int lc = sub + (q << 3);
                uint4 xv = W4[rb | (lc ^ m)];
                float4 ca = ((const float4*)cvec)[lc * 2];
                float4 cb = ((const float4*)cvec)[lc * 2 + 1];
                float f0,f1,f2,f3,f4,f5,f6,f7;
                h2f2(xv.x, f0, f1); h2f2(xv.y, f2, f3);
                h2f2(xv.z, f4, f5); h2f2(xv.w, f6, f7);
                float4 o0, o1;
                o0.x = r * f0 * ca.x;  o0.y = r * f1 * ca.y;
                o0.z = r * f2 * ca.z;  o0.w = r * f3 * ca.w;
                o1.x = r * f4 * cb.x;  o1.y = r * f5 * cb.y;
                o1.z = r * f6 * cb.z;  o1.w = r * f7 * cb.w;
                float4* rowY = (float4*)(Y + i * N + lc * 8);
                stcs4(rowY,     o0);
                stcs4(rowY + 1, o1);
            }
        }
    }
}

extern "C" void kernel_launch(void* const* d_in, const int* in_sizes, int n_in,
                              void* d_out, int out_size)
{
    const float* x = (const float*)d_in[0];
    float*       y = (float*)d_out;

    cudaFuncSetAttribute(sinkhorn_kernel,
                         cudaFuncAttributeMaxDynamicSharedMemorySize, SMEM_BYTES);
    sinkhorn_kernel<<<NMAT, THREADS, SMEM_BYTES>>>(x, y);
}

// round 11
// speedup vs baseline: 1.0115x; 1.0115x over previous
#include <cuda_runtime.h>
#include <cstdint>

#define NMAT    128
#define N       256
#define THREADS 1024

// smem (bytes): W4 131072 | part 16384 | c2 512 | cvec 1024
#define SMEM_BYTES (131072 + 16384 + 512 + 1024)

__device__ __forceinline__ uint32_t hfma2(uint32_t a, uint32_t b, uint32_t c) {
    uint32_t d; asm("fma.rn.f16x2 %0,%1,%2,%3;" : "=r"(d) : "r"(a), "r"(b), "r"(c)); return d;
}
__device__ __forceinline__ uint32_t hmul2(uint32_t a, uint32_t b) {
    uint32_t d; asm("mul.rn.f16x2 %0,%1,%2;" : "=r"(d) : "r"(a), "r"(b)); return d;
}
__device__ __forceinline__ uint32_t hadd2(uint32_t a, uint32_t b) {
    uint32_t d; asm("add.rn.f16x2 %0,%1,%2;" : "=r"(d) : "r"(a), "r"(b)); return d;
}
__device__ __forceinline__ uint32_t pk(float lo, float hi) {
    uint32_t d; asm("cvt.rn.f16x2.f32 %0, %1, %2;" : "=r"(d) : "f"(hi), "f"(lo)); return d;
}
__device__ __forceinline__ void h2f2(uint32_t w, float& lo, float& hi) {
    asm("{\n\t.reg .f16 l, h;\n\tmov.b32 {l, h}, %2;\n\tcvt.f32.f16 %0, l;\n\tcvt.f32.f16 %1, h;\n\t}"
        : "=f"(lo), "=f"(hi) : "r"(w));
}
__device__ __forceinline__ float frcp(float x) {
    float r; asm("rcp.approx.f32 %0, %1;" : "=f"(r) : "f"(x)); return r;
}
__device__ __forceinline__ void stcs4(float4* p, float4 v) {
    asm volatile("st.global.cs.v4.f32 [%0], {%1,%2,%3,%4};"
                 :: "l"(p), "f"(v.x), "f"(v.y), "f"(v.z), "f"(v.w) : "memory");
}

__global__ void __launch_bounds__(THREADS, 1)
sinkhorn_kernel(const float* __restrict__ x, float* __restrict__ y)
{
    extern __shared__ uint32_t smem_raw[];
    uint4*    W4   = (uint4*)smem_raw;                  // [256][32] chunks, XOR-swizzled
    uint4*    part = (uint4*)(smem_raw + 32768);        // [32][32] partial tile (reused)
    uint32_t* c2   = smem_raw + 36864;                  // [128] f16x2 (1/S1 pairs)
    float*    cvec = (float*)(smem_raw + 36992);        // [256] f32 (1/S2)

    const int tid = threadIdx.x;
    const int w   = tid >> 5;       // warp 0..31
    const int l   = tid & 31;       // lane
    const int g   = l >> 3;         // 8-lane group 0..3
    const int sub = l & 7;          // lane-in-group

    const float* __restrict__ X = x + (size_t)blockIdx.x * (N * N);
    float*       __restrict__ Y = y + (size_t)blockIdx.x * (N * N);

    // ==== Load fp32 -> fp16x2 smem (XOR swizzle) + fused iter-1 Phase A partials ====
    // Fully unrolled: all 16 LDG.128 independent -> max MLP against DRAM latency.
    {
        const float4* __restrict__ Xv = (const float4*)X;
        float s0=0.f,s1=0.f,s2=0.f,s3=0.f,s4=0.f,s5=0.f,s6=0.f,s7=0.f;
        #pragma unroll
        for (int k = 0; k < 8; ++k) {
            const int row = w + (k << 5);
            const int lin = (row << 5) | l;
            float4 a = Xv[2 * lin];
            float4 b = Xv[2 * lin + 1];
            uint4 wv;
            wv.x = pk(a.x, a.y); wv.y = pk(a.z, a.w);
            wv.z = pk(b.x, b.y); wv.w = pk(b.z, b.w);
            W4[(row << 5) | (l ^ w)] = wv;
            s0 += a.x; s1 += a.y; s2 += a.z; s3 += a.w;
            s4 += b.x; s5 += b.y; s6 += b.z; s7 += b.w;
        }
        uint4 pv;
        pv.x = pk(s0, s1); pv.y = pk(s2, s3);
        pv.z = pk(s4, s5); pv.w = pk(s6, s7);
        part[(w << 5) | (l ^ w)] = pv;       // logical part[rg=w][chunk=l]
    }
    __syncthreads();

    // ==== A1 reduce: warp w reduces chunk-column w -> c2 ====
    {
        uint4 pv = part[(l << 5) | (w ^ l)];  // logical part[rg=l][chunk=w]
        uint32_t a0 = pv.x, a1 = pv.y, a2 = pv.z, a3 = pv.w;
        #pragma unroll
        for (int o = 16; o; o >>= 1) {
            a0 = hadd2(a0, __shfl_xor_sync(0xffffffffu, a0, o));
            a1 = hadd2(a1, __shfl_xor_sync(0xffffffffu, a1, o));
            a2 = hadd2(a2, __shfl_xor_sync(0xffffffffu, a2, o));
            a3 = hadd2(a3, __shfl_xor_sync(0xffffffffu, a3, o));
        }
        if (l < 4) {
            uint32_t s = (l == 0) ? a0 : (l == 1) ? a1 : (l == 2) ? a2 : a3;
            float lo, hi; h2f2(s, lo, hi);
            c2[(w << 2) | l] = pk(frcp(lo), frcp(hi));
        }
    }
    __syncthreads();

    // ==== B1 (fp16 row sums with c1) FUSED with A2 partial accumulation ====
    {
        uint32_t acc[16];
        #pragma unroll
        for (int j = 0; j < 16; ++j) acc[j] = 0u;

        #pragma unroll
        for (int step = 0; step < 2; ++step) {
            const int i  = (w << 3) | (step << 2) | g;
            const int m  = i & 31;
            const int rb = i << 5;
            uint4 xq0, xq1, xq2, xq3;
            uint32_t p0, p1, p2, p3;
            {
                xq0 = W4[rb | ( sub        ^ m)];
                const uint4 cq = ((const uint4*)c2)[sub];
                p0 = hmul2(xq0.x, cq.x);
                p0 = hfma2(xq0.y, cq.y, p0); p0 = hfma2(xq0.z, cq.z, p0); p0 = hfma2(xq0.w, cq.w, p0);
            }
            {
                xq1 = W4[rb | ((sub +  8) ^ m)];
                const uint4 cq = ((const uint4*)c2)[sub + 8];
                p1 = hmul2(xq1.x, cq.x);
                p1 = hfma2(xq1.y, cq.y, p1); p1 = hfma2(xq1.z, cq.z, p1); p1 = hfma2(xq1.w, cq.w, p1);
            }
            {
                xq2 = W4[rb | ((sub + 16) ^ m)];
                const uint4 cq = ((const uint4*)c2)[sub + 16];
                p2 = hmul2(xq2.x, cq.x);
                p2 = hfma2(xq2.y, cq.y, p2); p2 = hfma2(xq2.z, cq.z, p2); p2 = hfma2(xq2.w, cq.w, p2);
            }
            {
                xq3 = W4[rb | ((sub + 24) ^ m)];
                const uint4 cq = ((const uint4*)c2)[sub + 24];
                p3 = hmul2(xq3.x, cq.x);
                p3 = hfma2(xq3.y, cq.y, p3); p3 = hfma2(xq3.z, cq.z, p3); p3 = hfma2(xq3.w, cq.w, p3);
            }
            uint32_t ps = hadd2(hadd2(p0, p1), hadd2(p2, p3));
            float lo, hi; h2f2(ps, lo, hi);
            float t = lo + hi;
            t += __shfl_xor_sync(0xffffffffu, t, 1);
            t += __shfl_xor_sync(0xffffffffu, t, 2);
            t += __shfl_xor_sync(0xffffffffu, t, 4);
            const float r = frcp(t);
            const uint32_t rp = pk(r, r);
            acc[0]  = hfma2(rp, xq0.x, acc[0]);  acc[1]  = hfma2(rp, xq0.y, acc[1]);
            acc[2]  = hfma2(rp, xq0.z, acc[2]);  acc[3]  = hfma2(rp, xq0.w, acc[3]);
            acc[4]  = hfma2(rp, xq1.x, acc[4]);  acc[5]  = hfma2(rp, xq1.y, acc[5]);
            acc[6]  = hfma2(rp, xq1.z, acc[6]);  acc[7]  = hfma2(rp, xq1.w, acc[7]);
            acc[8]  = hfma2(rp, xq2.x, acc[8]);  acc[9]  = hfma2(rp, xq2.y, acc[9]);
            acc[10] = hfma2(rp, xq2.z, acc[10]); acc[11] = hfma2(rp, xq2.w, acc[11]);
            acc[12] = hfma2(rp, xq3.x, acc[12]); acc[13] = hfma2(rp, xq3.y, acc[13]);
            acc[14] = hfma2(rp, xq3.z, acc[14]); acc[15] = hfma2(rp, xq3.w, acc[15]);
        }
        // reduce over the 4 lane-groups (same sub, g=0..3)
        #pragma unroll
        for (int j = 0; j < 16; ++j) {
            acc[j] = hadd2(acc[j], __shfl_xor_sync(0xffffffffu, acc[j], 8));
            acc[j] = hadd2(acc[j], __shfl_xor_sync(0xffffffffu, acc[j], 16));
        }
        if (l < 8) {          // lane sub==l holds warp partials for chunks {l, l+8, l+16, l+24}
            #pragma unroll
            for (int q = 0; q < 4; ++q) {
                const int c = l + (q << 3);
                uint4 v;
                v.x = acc[q * 4 + 0]; v.y = acc[q * 4 + 1];
                v.z = acc[q * 4 + 2]; v.w = acc[q * 4 + 3];
                part[(w << 5) | (c ^ w)] = v;    // logical part[v=w][chunk=c]
            }
        }
    }
    __syncthreads();

    // ==== A2 reduce (fp32 butterfly over 32 warp-partials) -> cvec ====
    {
        uint4 pv = part[(l << 5) | (w ^ l)];     // logical part[v=l][chunk=w]
        float s0,s1,s2,s3,s4,s5,s6,s7;
        h2f2(pv.x, s0, s1); h2f2(pv.y, s2, s3);
        h2f2(pv.z, s4, s5); h2f2(pv.w, s6, s7);
        #pragma unroll
        for (int o = 16; o; o >>= 1) {
            s0 += __shfl_xor_sync(0xffffffffu, s0, o);
            s1 += __shfl_xor_sync(0xffffffffu, s1, o);
            s2 += __shfl_xor_sync(0xffffffffu, s2, o);
            s3 += __shfl_xor_sync(0xffffffffu, s3, o);
            s4 += __shfl_xor_sync(0xffffffffu, s4, o);
            s5 += __shfl_xor_sync(0xffffffffu, s5, o);
            s6 += __shfl_xor_sync(0xffffffffu, s6, o);
            s7 += __shfl_xor_sync(0xffffffffu, s7, o);
        }
        if (l < 8) {
            float v = (l==0)?s0:(l==1)?s1:(l==2)?s2:(l==3)?s3:(l==4)?s4:(l==5)?s5:(l==6)?s6:s7;
            cvec[(w << 3) | l] = frcp(v);
        }
    }
    __syncthreads();

    // ==== B2 (fp32 row sums with c2) FUSED with output; chunks register-cached ====
    {
        #pragma unroll
        for (int step = 0; step < 2; ++step) {
            const int i  = (w << 3) | (step << 2) | g;
            const int m  = i & 31;
            const int rb = i << 5;
            uint4 xq[4];
            float ta = 0.f, tb = 0.f;
            #pragma unroll
            for (int q = 0; q < 4; ++q) {
                const int lc = sub + (q << 3);
                xq[q] = W4[rb | (lc ^ m)];
                float4 ca = ((const float4*)cvec)[lc * 2];
                float4 cb = ((const float4*)cvec)[lc * 2 + 1];
                float f0,f1,f2,f3,f4,f5,f6,f7;
                h2f2(xq[q].x, f0, f1); h2f2(xq[q].y, f2, f3);
                h2f2(xq[q].z, f4, f5); h2f2(xq[q].w, f6, f7);
                ta = fmaf(f0, ca.x, ta); tb = fmaf(f1, ca.y, tb);
                ta = fmaf(f2, ca.z, ta); tb = fmaf(f3, ca.w, tb);
                ta = fmaf(f4, cb.x, ta); tb = fmaf(f5, cb.y, tb);
                ta = fmaf(f6, cb.z, ta); tb = fmaf(f7, cb.w, tb);
            }
            float t = ta + tb;
            t += __shfl_xor_sync(0xffffffffu, t, 1);
            t += __shfl_xor_sync(0xffffffffu, t, 2);
            t += __shfl_xor_sync(0xffffffffu, t, 4);
            const float r = frcp(t);

            // output from register-cached chunks: no smem re-read
            #pragma unroll
            for (int q = 0; q < 4; ++q) {
                const int lc = sub + (q << 3);
                float4 ca = ((const float4*)cvec)[lc * 2];
                float4 cb = ((const float4*)cvec)[lc * 2 + 1];
                float f0,f1,f2,f3,f4,f5,f6,f7;
                h2f2(xq[q].x, f0, f1); h2f2(xq[q].y, f2, f3);
                h2f2(xq[q].z, f4, f5); h2f2(xq[q].w, f6, f7);
                float4 o0, o1;
                o0.x = r * f0 * ca.x;  o0.y = r * f1 * ca.y;
                o0.z = r * f2 * ca.z;  o0.w = r * f3 * ca.w;
                o1.x = r * f4 * cb.x;  o1.y = r * f5 * cb.y;
                o1.z = r * f6 * cb.z;  o1.w = r * f7 * cb.w;
                float4* rowY = (float4*)(Y + i * N + lc * 8);
                stcs4(rowY,     o0);
                stcs4(rowY + 1, o1);
            }
        }
    }
}

extern "C" void kernel_launch(void* const* d_in, const int* in_sizes, int n_in,
                              void* d_out, int out_size)
{
    const float* x = (const float*)d_in[0];
    float*       y = (float*)d_out;

    cudaFuncSetAttribute(sinkhorn_kernel,
                         cudaFuncAttributeMaxDynamicSharedMemorySize, SMEM_BYTES);
    sinkhorn_kernel<<<NMAT, THREADS, SMEM_BYTES>>>(x, y);
}

// round 12
// speedup vs baseline: 1.0703x; 1.0581x over previous
#include <cuda_runtime.h>
#include <cstdint>

#define NMAT    128
#define N       256
#define THREADS 512

// Per-CTA smem word offsets (32-bit words):
//  W     [256 rows][16 chunks] uint4   words     0..16383  (65536 B)
//  P     [16][16] uint4 (A1 partials)  words 16384..17407  ( 4096 B)
//  c1    [16] uint4                    words 17408..17471  (  256 B)
//  cvec2 [128] f32                     words 17472..17599  (  512 B)
//  rvec  [256] f32                     words 17600..17855  ( 1024 B)
//  Tl    [256] f32 (reused for Tl2)    words 17856..18111  ( 1024 B)
//  Tp1   [256] f32 (recv from partner) words 18112..18367  ( 1024 B)
//  Tp2   [256] f32 (recv from partner) words 18368..18623  ( 1024 B)
#define SMEM_WORDS 18624
#define SMEM_BYTES (SMEM_WORDS * 4)
#define OFF_P     16384
#define OFF_C1    17408
#define OFF_CV2   17472
#define OFF_RV    17600
#define OFF_TL    17856
#define OFF_TP1   18112
#define OFF_TP2   18368

__device__ __forceinline__ uint32_t hfma2(uint32_t a, uint32_t b, uint32_t c) {
    uint32_t d; asm("fma.rn.f16x2 %0,%1,%2,%3;" : "=r"(d) : "r"(a), "r"(b), "r"(c)); return d;
}
__device__ __forceinline__ uint32_t hmul2(uint32_t a, uint32_t b) {
    uint32_t d; asm("mul.rn.f16x2 %0,%1,%2;" : "=r"(d) : "r"(a), "r"(b)); return d;
}
__device__ __forceinline__ uint32_t hadd2(uint32_t a, uint32_t b) {
    uint32_t d; asm("add.rn.f16x2 %0,%1,%2;" : "=r"(d) : "r"(a), "r"(b)); return d;
}
__device__ __forceinline__ uint32_t pk(float lo, float hi) {
    uint32_t d; asm("cvt.rn.f16x2.f32 %0, %1, %2;" : "=r"(d) : "f"(hi), "f"(lo)); return d;
}
__device__ __forceinline__ void h2f2(uint32_t w, float& lo, float& hi) {
    asm("{\n\t.reg .f16 l, h;\n\tmov.b32 {l, h}, %2;\n\tcvt.f32.f16 %0, l;\n\tcvt.f32.f16 %1, h;\n\t}"
        : "=f"(lo), "=f"(hi) : "r"(w));
}
__device__ __forceinline__ float frcp(float x) {
    float r; asm("rcp.approx.f32 %0, %1;" : "=f"(r) : "f"(x)); return r;
}
__device__ __forceinline__ void stcs4(float4* p, float4 v) {
    asm volatile("st.global.cs.v4.f32 [%0], {%1,%2,%3,%4};"
                 :: "l"(p), "f"(v.x), "f"(v.y), "f"(v.z), "f"(v.w) : "memory");
}
__device__ __forceinline__ uint32_t smem_u32(const void* p) {
    uint32_t a;
    asm("{ .reg .u64 t; cvta.to.shared.u64 t, %1; cvt.u32.u64 %0, t; }" : "=r"(a) : "l"(p));
    return a;
}
__device__ __forceinline__ uint32_t mapa_u32(uint32_t local_addr, uint32_t rank) {
    uint32_t r;
    asm("mapa.shared::cluster.u32 %0, %1, %2;" : "=r"(r) : "r"(local_addr), "r"(rank));
    return r;
}
__device__ __forceinline__ void st_cluster_f32(uint32_t addr, float v) {
    asm volatile("st.shared::cluster.f32 [%0], %1;" :: "r"(addr), "f"(v) : "memory");
}
#define CLUSTER_SYNC() do { \
    asm volatile("barrier.cluster.arrive.aligned;" ::: "memory"); \
    asm volatile("barrier.cluster.wait.aligned;"   ::: "memory"); \
} while (0)

__global__ void __launch_bounds__(THREADS, 2) __cluster_dims__(2, 1, 1)
sinkhorn_kernel(const float* __restrict__ x, float* __restrict__ y)
{
    extern __shared__ uint32_t smem_raw[];
    uint4*  W     = (uint4*)smem_raw;
    uint4*  P     = (uint4*)(smem_raw + OFF_P);
    uint4*  c1    = (uint4*)(smem_raw + OFF_C1);
    float*  cvec2 = (float*)(smem_raw + OFF_CV2);
    float*  rvec  = (float*)(smem_raw + OFF_RV);
    float*  Tl    = (float*)(smem_raw + OFF_TL);
    float*  Tp1   = (float*)(smem_raw + OFF_TP1);
    float*  Tp2   = (float*)(smem_raw + OFF_TP2);

    const int tid = threadIdx.x;
    const int w   = tid >> 5;        // warp 0..15
    const int l   = tid & 31;        // lane
    const int p   = l >> 4;          // row-parity half 0/1
    const int c   = l & 15;          // local chunk 0..15 (8 cols each)

    const int m = blockIdx.x >> 1;   // matrix
    const int h = blockIdx.x & 1;    // column half == cluster rank

    const float*  X  = x + (size_t)m * (N * N);
    float*        Y  = y + (size_t)m * (N * N);
    const float4* Xv = (const float4*)X;

    const uint32_t smem_base = smem_u32(smem_raw);
    const uint32_t remTp1 = mapa_u32(smem_base + OFF_TP1 * 4, (uint32_t)(h ^ 1));
    const uint32_t remTp2 = mapa_u32(smem_base + OFF_TP2 * 4, (uint32_t)(h ^ 1));

    const int pc = c ^ w;            // phys chunk for rows ≡ w (mod 16)

    // ==== Load fp32 -> fp16x2 smem (swizzled) + fused A1 fp32 partials ====
    {
        float s0=0.f,s1=0.f,s2=0.f,s3=0.f,s4=0.f,s5=0.f,s6=0.f,s7=0.f;
        #pragma unroll
        for (int k = 0; k < 8; ++k) {
            const int j   = (k << 1) | p;
            const int row = w + (j << 4);             // row & 15 == w
            const int fi  = (row << 6) + (h << 5) + (c << 1);
            float4 a = Xv[fi];
            float4 b = Xv[fi + 1];
            uint4 wv;
            wv.x = pk(a.x, a.y); wv.y = pk(a.z, a.w);
            wv.z = pk(b.x, b.y); wv.w = pk(b.z, b.w);
            W[(row << 4) | pc] = wv;
            s0 += a.x; s1 += a.y; s2 += a.z; s3 += a.w;
            s4 += b.x; s5 += b.y; s6 += b.z; s7 += b.w;
        }
        // merge parity halves (lane l <-> l^16): partial over rows {w+16j, j=0..15}
        s0 += __shfl_xor_sync(0xffffffffu, s0, 16);
        s1 += __shfl_xor_sync(0xffffffffu, s1, 16);
        s2 += __shfl_xor_sync(0xffffffffu, s2, 16);
        s3 += __shfl_xor_sync(0xffffffffu, s3, 16);
        s4 += __shfl_xor_sync(0xffffffffu, s4, 16);
        s5 += __shfl_xor_sync(0xffffffffu, s5, 16);
        s6 += __shfl_xor_sync(0xffffffffu, s6, 16);
        s7 += __shfl_xor_sync(0xffffffffu, s7, 16);
        if (p == 0) {
            uint4 pv;
            pv.x = pk(s0, s1); pv.y = pk(s2, s3);
            pv.z = pk(s4, s5); pv.w = pk(s6, s7);
            P[(w << 4) | (c ^ w)] = pv;               // logical P[warp=w][chunk=c]
        }
    }
    __syncthreads();

    // ==== A1 reduce: warp w reduces chunk w over 16 warp-partials -> c1[w] ====
    {
        uint4 pv = P[(c << 4) | (w ^ c)];             // logical P[warp=c][chunk=w]
        uint32_t a0 = pv.x, a1 = pv.y, a2 = pv.z, a3 = pv.w;
        #pragma unroll
        for (int o = 8; o; o >>= 1) {
            a0 = hadd2(a0, __shfl_xor_sync(0xffffffffu, a0, o));
            a1 = hadd2(a1, __shfl_xor_sync(0xffffffffu, a1, o));
            a2 = hadd2(a2, __shfl_xor_sync(0xffffffffu, a2, o));
            a3 = hadd2(a3, __shfl_xor_sync(0xffffffffu, a3, o));
        }
        if (l == 0) {
            float f0,f1,f2,f3,f4,f5,f6,f7;
            h2f2(a0, f0, f1); h2f2(a1, f2, f3);
            h2f2(a2, f4, f5); h2f2(a3, f6, f7);
            uint4 cv;
            cv.x = pk(frcp(f0), frcp(f1)); cv.y = pk(frcp(f2), frcp(f3));
            cv.z = pk(frcp(f4), frcp(f5)); cv.w = pk(frcp(f6), frcp(f7));
            c1[w] = cv;
        }
    }
    __syncthreads();

    // ==== B1 (fp16): local row partials over own 128 cols; send to partner ====
    {
        const uint4 cq = c1[c];
        #pragma unroll
        for (int k = 0; k < 8; ++k) {
            const int row = w + ((((k << 1) | p)) << 4);
            uint4 xv = W[(row << 4) | pc];
            uint32_t ps = hmul2(xv.x, cq.x);
            ps = hfma2(xv.y, cq.y, ps);
            ps = hfma2(xv.z, cq.z, ps);
            ps = hfma2(xv.w, cq.w, ps);
            float lo, hi; h2f2(ps, lo, hi);
            float t = lo + hi;
            t += __shfl_xor_sync(0xffffffffu, t, 1);
            t += __shfl_xor_sync(0xffffffffu, t, 2);
            t += __shfl_xor_sync(0xffffffffu, t, 4);
            t += __shfl_xor_sync(0xffffffffu, t, 8);   // 16-lane group sum
            if (c == 0) {
                Tl[row] = t;
                st_cluster_f32(remTp1 + (row << 2), t);
            }
        }
    }
    CLUSTER_SYNC();

    // ==== r1 = 1/(Tl + Tp1) ====
    if (tid < 256) rvec[tid] = frcp(Tl[tid] + Tp1[tid]);
    __syncthreads();

    // ==== A2 (fp32): warp w owns chunk w; weighted column sums -> cvec2 ====
    {
        float s0=0.f,s1=0.f,s2=0.f,s3=0.f,s4=0.f,s5=0.f,s6=0.f,s7=0.f;
        const int pcA = w ^ (l & 15);
        #pragma unroll
        for (int k = 0; k < 8; ++k) {
            const int row = l + (k << 5);
            const float rr = rvec[row];
            uint4 xv = W[(row << 4) | pcA];
            float f0,f1,f2,f3,f4,f5,f6,f7;
            h2f2(xv.x, f0, f1); h2f2(xv.y, f2, f3);
            h2f2(xv.z, f4, f5); h2f2(xv.w, f6, f7);
            s0 = fmaf(rr, f0, s0); s1 = fmaf(rr, f1, s1);
            s2 = fmaf(rr, f2, s2); s3 = fmaf(rr, f3, s3);
            s4 = fmaf(rr, f4, s4); s5 = fmaf(rr, f5, s5);
            s6 = fmaf(rr, f6, s6); s7 = fmaf(rr, f7, s7);
        }
        #pragma unroll
        for (int o = 16; o; o >>= 1) {
            s0 += __shfl_xor_sync(0xffffffffu, s0, o);
            s1 += __shfl_xor_sync(0xffffffffu, s1, o);
            s2 += __shfl_xor_sync(0xffffffffu, s2, o);
            s3 += __shfl_xor_sync(0xffffffffu, s3, o);
            s4 += __shfl_xor_sync(0xffffffffu, s4, o);
            s5 += __shfl_xor_sync(0xffffffffu, s5, o);
            s6 += __shfl_xor_sync(0xffffffffu, s6, o);
            s7 += __shfl_xor_sync(0xffffffffu, s7, o);
        }
        if (l < 8) {
            float v = (l==0)?s0:(l==1)?s1:(l==2)?s2:(l==3)?s3:(l==4)?s4:(l==5)?s5:(l==6)?s6:s7;
            cvec2[(w << 3) | l] = frcp(v);
        }
    }
    __syncthreads();

    // ==== B2 (fp32): local row partials with c2; send to partner ====
    {
        const float4 ca = ((const float4*)cvec2)[c * 2];
        const float4 cb = ((const float4*)cvec2)[c * 2 + 1];
        #pragma unroll
        for (int k = 0; k < 8; ++k) {
            const int row = w + ((((k << 1) | p)) << 4);
            uint4 xv = W[(row << 4) | pc];
            float f0,f1,f2,f3,f4,f5,f6,f7;
            h2f2(xv.x, f0, f1); h2f2(xv.y, f2, f3);
            h2f2(xv.z, f4, f5); h2f2(xv.w, f6, f7);
            float ta = f0 * ca.x + f1 * ca.y + f2 * ca.z + f3 * ca.w;
            float tb = f4 * cb.x + f5 * cb.y + f6 * cb.z + f7 * cb.w;
            float t = ta + tb;
            t += __shfl_xor_sync(0xffffffffu, t, 1);
            t += __shfl_xor_sync(0xffffffffu, t, 2);
            t += __shfl_xor_sync(0xffffffffu, t, 4);
            t += __shfl_xor_sync(0xffffffffu, t, 8);
            if (c == 0) {
                Tl[row] = t;                          // Tl reused as Tl2
                st_cluster_f32(remTp2 + (row << 2), t);
            }
        }
    }
    CLUSTER_SYNC();

    // ==== Output: y = r2 * x * c2 over own 128 cols ====
    {
        const float4 ca = ((const float4*)cvec2)[c * 2];
        const float4 cb = ((const float4*)cvec2)[c * 2 + 1];
        #pragma unroll
        for (int k = 0; k < 8; ++k) {
            const int row = w + ((((k << 1) | p)) << 4);
            const float r2 = frcp(Tl[row] + Tp2[row]);
            uint4 xv = W[(row << 4) | pc];
            float f0,f1,f2,f3,f4,f5,f6,f7;
            h2f2(xv.x, f0, f1); h2f2(xv.y, f2, f3);
            h2f2(xv.z, f4, f5); h2f2(xv.w, f6, f7);
            float4 o0, o1;
            o0.x = r2 * f0 * ca.x;  o0.y = r2 * f1 * ca.y;
            o0.z = r2 * f2 * ca.z;  o0.w = r2 * f3 * ca.w;
            o1.x = r2 * f4 * cb.x;  o1.y = r2 * f5 * cb.y;
            o1.z = r2 * f6 * cb.z;  o1.w = r2 * f7 * cb.w;
            float4* rowY = (float4*)(Y + (row << 8) + (h << 7) + (c << 3));
            stcs4(rowY,     o0);
            stcs4(rowY + 1, o1);
        }
    }
}

extern "C" void kernel_launch(void* const* d_in, const int* in_sizes, int n_in,
                              void* d_out, int out_size)
{
    const float* x = (const float*)d_in[0];
    float*       y = (float*)d_out;

    cudaFuncSetAttribute(sinkhorn_kernel,
                         cudaFuncAttributeMaxDynamicSharedMemorySize, SMEM_BYTES);
    sinkhorn_kernel<<<NMAT * 2, THREADS, SMEM_BYTES>>>(x, y);
}